// round 10
// baseline (speedup 1.0000x reference)
#include <cuda_runtime.h>
#include <cstdint>

// Problem constants
#define BSZ     8
#define KDIM    4096
#define NDIM    11008
#define RPW     4                        // rows per warp task
#define SPLITK  4                        // K-chunks == warps per quad
#define KCH     (KDIM / SPLITK)          // 1024 floats per K-chunk
#define KITERS  (KCH / 128)              // 8 iterations (128 floats/row/iter)
#define WARPS_PER_CTA 16
#define THREADS (WARPS_PER_CTA * 32)     // 512
#define NCTAS   148
#define QUADS_PER_CTA 4
#define NQUADS  (NCTAS * QUADS_PER_CTA)  // 592
#define NROWGROUPS (NDIM / RPW)          // 2752
#define XS_BYTES (BSZ * KDIM * 4)        // 131072
// reduction scratch: [parity][quad][warp][32 floats] = 2*4*4*128B = 4096
#define RED_BYTES (2 * QUADS_PER_CTA * SPLITK * 32 * 4)
#define SMEM_BYTES (XS_BYTES + RED_BYTES)

typedef unsigned long long ull;

// ---- packed f32x2 FMA (Blackwell f32x2 pipe) ----
__device__ __forceinline__ void ffma2(ull& d, ull a, ull b) {
    asm("fma.rn.f32x2 %0, %1, %2, %0;" : "+l"(d) : "l"(a), "l"(b));
}
__device__ __forceinline__ float sum2(ull a) {
    float lo, hi;
    asm("mov.b64 {%0, %1}, %2;" : "=f"(lo), "=f"(hi) : "l"(a));
    return lo + hi;
}
// streaming 128-bit global load as two packed f32x2 words (bypass L1 reuse)
__device__ __forceinline__ void ldg_cs_v2u64(const void* p, ull& a, ull& b) {
    asm("ld.global.cs.v2.u64 {%0, %1}, [%2];"
        : "=l"(a), "=l"(b) : "l"(p));
}

extern __shared__ float xs[];   // [BSZ][KDIM] x, then red scratch

__global__ __launch_bounds__(THREADS, 1)
void asl_gemv_kernel(const float* __restrict__ x,
                     const float* __restrict__ w,
                     float* __restrict__ out) {
    // ---- stage x into shared memory (131 KB), once per CTA ----
    {
        const float4* x4  = reinterpret_cast<const float4*>(x);
        float4*       xs4 = reinterpret_cast<float4*>(xs);
        #pragma unroll 8
        for (int i = threadIdx.x; i < BSZ * KDIM / 4; i += THREADS)
            xs4[i] = x4[i];
    }
    __syncthreads();

    const int lane = threadIdx.x & 31;
    const int wid  = threadIdx.x >> 5;
    const int q    = wid >> 2;            // quad 0..3
    const int kc   = wid & 3;             // K-chunk handled by this warp
    const int gquad = blockIdx.x * QUADS_PER_CTA + q;
    const int kbase = kc * KCH;

    const ulonglong2* xs2 = reinterpret_cast<const ulonglong2*>(xs);
    float* red = xs + BSZ * KDIM;         // [parity][q][w][32]

    for (int step = 0, rg = gquad; rg < NROWGROUPS; step++, rg += NQUADS) {
        const int n0 = rg * RPW;
        const char* wr = reinterpret_cast<const char*>(
            w + (size_t)n0 * KDIM + kbase);
        const ulonglong2* xb = xs2 + (kbase >> 2);  // x chunk base (16B units)

        ull acc[RPW][BSZ];
        #pragma unroll
        for (int r = 0; r < RPW; r++)
            #pragma unroll
            for (int b = 0; b < BSZ; b++)
                acc[r][b] = 0ULL;

        #pragma unroll 2
        for (int it = 0; it < KITERS; it++) {
            const int koff = (it * 32 + lane) * 16;   // byte offset in chunk

            ull w0l, w0h, w1l, w1h, w2l, w2h, w3l, w3h;
            ldg_cs_v2u64(wr +                 koff, w0l, w0h);
            ldg_cs_v2u64(wr +     KDIM * 4 +  koff, w1l, w1h);
            ldg_cs_v2u64(wr + 2 * KDIM * 4 +  koff, w2l, w2h);
            ldg_cs_v2u64(wr + 3 * KDIM * 4 +  koff, w3l, w3h);

            const int xoff = it * 32 + lane;          // 16B-unit offset
            #pragma unroll
            for (int b = 0; b < BSZ; b++) {
                ulonglong2 xv = xb[b * (KDIM / 4) + xoff];
                ffma2(acc[0][b], w0l, xv.x); ffma2(acc[0][b], w0h, xv.y);
                ffma2(acc[1][b], w1l, xv.x); ffma2(acc[1][b], w1h, xv.y);
                ffma2(acc[2][b], w2l, xv.x); ffma2(acc[2][b], w2h, xv.y);
                ffma2(acc[3][b], w3l, xv.x); ffma2(acc[3][b], w3h, xv.y);
            }
        }

        // ---- butterfly: 32 partials across 32 lanes in 31 SHFL ----
        // v[i] <-> (r = i & 3, b = i >> 2); after 5 rounds lane l holds v[l].
        float v[32];
        #pragma unroll
        for (int b = 0; b < BSZ; b++)
            #pragma unroll
            for (int r = 0; r < RPW; r++)
                v[b * RPW + r] = sum2(acc[r][b]);

        #pragma unroll
        for (int s = 16; s >= 1; s >>= 1) {
            const bool hi = (lane & s) != 0;
            #pragma unroll
            for (int j = 0; j < s; j++) {
                float mine  = hi ? v[j + s] : v[j];
                float sent  = hi ? v[j]     : v[j + s];
                float other = __shfl_xor_sync(0xFFFFFFFFu, sent, s);
                v[j] = mine + other;
            }
        }

        // ---- quad reduction over the 4 K-chunks, then direct store ----
        const int parity = step & 1;
        float* redq = red + (parity * QUADS_PER_CTA + q) * (SPLITK * 32);
        redq[kc * 32 + lane] = v[0];

        asm volatile("bar.sync %0, 128;" :: "r"(q + 1) : "memory");

        if (lane < 8) {
            const int i = kc * 8 + lane;          // 0..31: (r = i&3, b = i>>2)
            float s = (redq[i] + redq[32 + i]) +
                      (redq[64 + i] + redq[96 + i]);
            out[(size_t)(i >> 2) * NDIM + n0 + (i & 3)] = s;
        }
    }
}

extern "C" void kernel_launch(void* const* d_in, const int* in_sizes, int n_in,
                              void* d_out, int out_size) {
    const float* x = (const float*)d_in[0];
    const float* w = (const float*)d_in[1];
    if (n_in >= 2 && in_sizes[0] == NDIM * KDIM) {   // defensive order fix
        const float* t = x; x = w; w = t;
    }
    float* out = (float*)d_out;

    cudaFuncSetAttribute(asl_gemv_kernel,
                         cudaFuncAttributeMaxDynamicSharedMemorySize,
                         SMEM_BYTES);

    asl_gemv_kernel<<<NCTAS, THREADS, SMEM_BYTES>>>(x, w, out);
}